// round 10
// baseline (speedup 1.0000x reference)
#include <cuda_runtime.h>
#include <math.h>
#include <stdint.h>

#define BGRAPH  32768
#define NPAIR   (BGRAPH/2)
#define NPG     54
#define EPG     144
#define NTOT    (BGRAPH*NPG)
#define ETOT    (BGRAPH*EPG)
#define OSTRIDE 232            // 226 used, padded
#define GNN_GRID 1036          // 7 * 148: one wave at 7 CTAs/SM

// Scratch: embeds(216) per graph (mlp fills cols 216..225 itself).
__device__ __align__(16) float g_scratch[(size_t)BGRAPH * OSTRIDE];
// Column-major padded Wo1^T: [128 cols][228], built by gnn CTAs.
__device__ __align__(16) float g_Wo1T[128 * 228 + 16];

// ---------- packed fp32x2 helpers ----------
__device__ __forceinline__ void ffma2(unsigned long long& d,
                                      unsigned long long a,
                                      unsigned long long b) {
    asm("fma.rn.f32x2 %0, %1, %2, %0;" : "+l"(d) : "l"(a), "l"(b));
}
__device__ __forceinline__ unsigned long long pack2(float lo, float hi) {
    unsigned long long r;
    asm("mov.b64 %0, {%1, %2};" : "=l"(r) : "f"(lo), "f"(hi));
    return r;
}
__device__ __forceinline__ void unpack2(float& lo, float& hi, unsigned long long v) {
    asm("mov.b64 {%0, %1}, %2;" : "=f"(lo), "=f"(hi) : "l"(v));
}

// ---------- cp.async helpers ----------
__device__ __forceinline__ uint32_t smem_u32(const void* p) {
    return (uint32_t)__cvta_generic_to_shared(p);
}
__device__ __forceinline__ void cpa16(uint32_t s, const void* g) {
    asm volatile("cp.async.cg.shared.global [%0], [%1], 16;" :: "r"(s), "l"(g));
}
__device__ __forceinline__ void cpa_commit() {
    asm volatile("cp.async.commit_group;");
}
__device__ __forceinline__ void cpa_wait0() {
    asm volatile("cp.async.wait_group 0;");
}
__device__ __forceinline__ void cpa_wait1() {
    asm volatile("cp.async.wait_group 1;");
}
// 64-thread named barrier (ids 1,2 — id 0 is __syncthreads)
__device__ __forceinline__ void bar64(int id) {
    asm volatile("bar.sync %0, 64;" :: "r"(id) : "memory");
}

// ============================================================================
// Kernel 1: persistent CTAs, 2 graphs per iteration (warp-group per graph),
// cp.async double buffer, named-barrier sync within each 2-warp group.
// Slot layout (floats): x:0(864=2x432) src:864(288) dst:1152(288) ea:1440(288)
// ============================================================================
#define SLOT_F  1728

__global__ void __launch_bounds__(128, 7) gnn_kernel(
    const float* __restrict__ x,  const int* __restrict__ ei,
    const float* __restrict__ ea,
    const float* __restrict__ Wrel1, const float* __restrict__ b1,
    const float* __restrict__ Wroot1,
    const float* __restrict__ Wrel2, const float* __restrict__ b2,
    const float* __restrict__ Wroot2,
    const float* __restrict__ Wo1)
{
    __shared__ __align__(16) float sW[484];
    __shared__ __align__(16) float sh1[2][NPG * 16];
    __shared__ __align__(16) float sagg1[2][NPG * 8]; // conv1 agg; reused as h2pre
    __shared__ __align__(16) float sagg2[2][NPG * 4];
    __shared__ int   shead[2][NPG];
    __shared__ int   snext[2][EPG];
    __shared__ int   ssrc[2][EPG];
    __shared__ __align__(16) float buf[2][SLOT_F];

    const int tid   = threadIdx.x;
    const int wg    = tid >> 6;          // 0: graph A (warps 0-1), 1: graph B
    const int sub   = (tid >> 5) & 1;    // warp within group
    const int lane  = tid & 31;
    const int tid64 = tid & 63;
    const int nstart = sub * 27;         // 27 nodes per warp

    // ---- build Wo1T cooperatively (write-once, consumed by mlp_kernel) ----
    {
        int gt = blockIdx.x * 128 + tid;
        if (gt < 226 * 128) {
            int j = gt / 226, k = gt - j * 226;
            g_Wo1T[j * 228 + k] = Wo1[k * 128 + j];
        }
    }

    // ---- build local transposed weights ----
    #pragma unroll
    for (int i = tid; i < 256; i += 128) {          // WT1
        int j = i >> 4, k = i & 15;
        sW[j * 20 + k] = (k < 8) ? Wrel1[k * 16 + j] : Wroot1[(k - 8) * 16 + j];
    }
    if (tid < 16) sW[320 + tid] = b1[tid];
    {                                               // WT2
        int j = tid >> 5, k = tid & 31;
        sW[336 + j * 36 + k] = (k < 16) ? Wrel2[k * 4 + j] : Wroot2[(k - 16) * 4 + j];
    }
    if (tid < 4)  sW[480 + tid] = b2[tid];
    if (tid < NPG) { shead[0][tid] = -1; shead[1][tid] = -1; }

    // ---- prefetch first pair ----
    int p0 = blockIdx.x;
    {
        uint32_t base = smem_u32(&buf[0][0]);
        const float* xg = x + (size_t)p0 * 2 * (NPG * 8);
        const int*   sg = ei + (size_t)p0 * 2 * EPG;
        const int*   dg = ei + (size_t)ETOT + (size_t)p0 * 2 * EPG;
        const float* eg = ea + (size_t)p0 * 2 * EPG;
        for (int i = tid; i < 432; i += 128) {
            if (i < 216)      cpa16(base + i * 16,                      xg + i * 4);
            else if (i < 288) cpa16(base + (864 * 4)  + (i - 216) * 16, sg + (i - 216) * 4);
            else if (i < 360) cpa16(base + (1152 * 4) + (i - 288) * 16, dg + (i - 288) * 4);
            else              cpa16(base + (1440 * 4) + (i - 360) * 16, eg + (i - 360) * 4);
        }
    }
    cpa_commit();

    int cur = 0;
    for (int pr = p0; pr < NPAIR; pr += GNN_GRID) {
        int prn = pr + GNN_GRID;
        if (prn < NPAIR) {       // prefetch next pair into other slot
            uint32_t base = smem_u32(&buf[cur ^ 1][0]);
            const float* xg = x + (size_t)prn * 2 * (NPG * 8);
            const int*   sg = ei + (size_t)prn * 2 * EPG;
            const int*   dg = ei + (size_t)ETOT + (size_t)prn * 2 * EPG;
            const float* eg = ea + (size_t)prn * 2 * EPG;
            for (int i = tid; i < 432; i += 128) {
                if (i < 216)      cpa16(base + i * 16,                      xg + i * 4);
                else if (i < 288) cpa16(base + (864 * 4)  + (i - 216) * 16, sg + (i - 216) * 4);
                else if (i < 360) cpa16(base + (1152 * 4) + (i - 288) * 16, dg + (i - 288) * 4);
                else              cpa16(base + (1440 * 4) + (i - 360) * 16, eg + (i - 360) * 4);
            }
            cpa_commit();
            cpa_wait1();
        } else {
            cpa_wait0();
        }
        __syncthreads();         // buffer + shead reset visible to all

        const int g = pr * 2 + wg;
        const float* bx  = &buf[cur][wg * 432];
        const int*   bs  = (const int*)&buf[cur][864 + wg * 144];
        const int*   bd  = (const int*)&buf[cur][1152 + wg * 144];
        const float* bea = &buf[cur][1440 + wg * 144];
        const int nbase = g * NPG;
        float* sh1g   = sh1[wg];
        float* sagg1g = sagg1[wg];
        float* sagg2g = sagg2[wg];
        int*   sheadg = shead[wg];
        int*   snextg = snext[wg];
        int*   ssrcg  = ssrc[wg];

        // ---- build per-destination edge linked lists (64 threads) ----
        for (int e = tid64; e < EPG; e += 64) {
            int d = bd[e] - nbase;
            ssrcg[e]  = bs[e] - nbase;
            snextg[e] = atomicExch(&sheadg[d], e);
        }
        bar64(1 + wg);

        // ---- conv1 agg over this warp's 27 nodes ----
        for (int i = lane; i < 54; i += 32) {
            int d = nstart + (i >> 1), c = i & 1;
            unsigned long long a0 = 0ull, a1 = 0ull;
            for (int e = sheadg[d]; e >= 0; e = snextg[e]) {
                unsigned long long ap = pack2(bea[e], bea[e]);
                ulonglong2 v = *reinterpret_cast<const ulonglong2*>(bx + ssrcg[e] * 8 + c * 4);
                ffma2(a0, v.x, ap); ffma2(a1, v.y, ap);
            }
            ulonglong2 r; r.x = a0; r.y = a1;
            *reinterpret_cast<ulonglong2*>(sagg1g + d * 8 + c * 4) = r;
        }
        __syncwarp();

        // ---- lin1: h1 = relu(agg1 @ Wrel1 + b1 + x @ Wroot1) ----
        for (int i = lane; i < 27 * 16; i += 32) {
            int n = nstart + (i >> 4), j = i & 15;
            const ulonglong2* ar = reinterpret_cast<const ulonglong2*>(sagg1g + n * 8);
            const ulonglong2* xr = reinterpret_cast<const ulonglong2*>(bx + n * 8);
            const ulonglong2* wr = reinterpret_cast<const ulonglong2*>(sW + j * 20);
            unsigned long long acc = 0ull;
            ulonglong2 w0 = wr[0], w1 = wr[1], w2 = wr[2], w3 = wr[3];
            ulonglong2 aa0 = ar[0], aa1 = ar[1], xx0 = xr[0], xx1 = xr[1];
            ffma2(acc, aa0.x, w0.x); ffma2(acc, aa0.y, w0.y);
            ffma2(acc, aa1.x, w1.x); ffma2(acc, aa1.y, w1.y);
            ffma2(acc, xx0.x, w2.x); ffma2(acc, xx0.y, w2.y);
            ffma2(acc, xx1.x, w3.x); ffma2(acc, xx1.y, w3.y);
            float lo, hi; unpack2(lo, hi, acc);
            sh1g[n * 16 + j] = fmaxf(lo + hi + sW[320 + j], 0.f);
        }
        bar64(1 + wg);           // BOTH warps done reading 8-wide sagg1 (lin1)
                                 // before h2pre overwrites it 4-wide (race fix)

        // ---- h2pre = h1 @ Wrel2 (own nodes; overwrites sagg1 as 4-wide) ----
        for (int i = lane; i < 27 * 4; i += 32) {
            int n = nstart + (i >> 2), j = i & 3;
            const ulonglong2* hr = reinterpret_cast<const ulonglong2*>(sh1g + n * 16);
            const ulonglong2* wr = reinterpret_cast<const ulonglong2*>(sW + 336 + j * 36);
            unsigned long long acc = 0ull;
            ulonglong2 w, v;
            w = wr[0]; v = hr[0]; ffma2(acc, v.x, w.x); ffma2(acc, v.y, w.y);
            w = wr[1]; v = hr[1]; ffma2(acc, v.x, w.x); ffma2(acc, v.y, w.y);
            w = wr[2]; v = hr[2]; ffma2(acc, v.x, w.x); ffma2(acc, v.y, w.y);
            w = wr[3]; v = hr[3]; ffma2(acc, v.x, w.x); ffma2(acc, v.y, w.y);
            float lo, hi; unpack2(lo, hi, acc);
            sagg1g[n * 4 + j] = lo + hi;
        }
        bar64(1 + wg);           // h2pre complete (conv2 walk reads cross-warp)

        // ---- conv2 aggregation, 4-wide: pair (2jp, 2jp+1) per item ----
        for (int i = lane; i < 54; i += 32) {
            int d = nstart + (i >> 1), jp = i & 1;
            unsigned long long acc = 0ull;
            for (int e = sheadg[d]; e >= 0; e = snextg[e]) {
                unsigned long long ap = pack2(bea[e], bea[e]);
                unsigned long long v = *reinterpret_cast<const unsigned long long*>(
                    sagg1g + ssrcg[e] * 4 + jp * 2);
                ffma2(acc, v, ap);
            }
            *reinterpret_cast<unsigned long long*>(sagg2g + d * 4 + jp * 2) = acc;
        }
        __syncwarp();

        // ---- lin2 (root half): og = relu(agg + h1 @ Wroot2 + b2) ----
        float* og = g_scratch + (size_t)g * OSTRIDE;
        for (int i = lane; i < 27 * 4; i += 32) {
            int n = nstart + (i >> 2), j = i & 3;
            const ulonglong2* hr = reinterpret_cast<const ulonglong2*>(sh1g + n * 16);
            const ulonglong2* wr = reinterpret_cast<const ulonglong2*>(sW + 336 + j * 36 + 16);
            unsigned long long acc = 0ull;
            ulonglong2 w, v;
            w = wr[0]; v = hr[0]; ffma2(acc, v.x, w.x); ffma2(acc, v.y, w.y);
            w = wr[1]; v = hr[1]; ffma2(acc, v.x, w.x); ffma2(acc, v.y, w.y);
            w = wr[2]; v = hr[2]; ffma2(acc, v.x, w.x); ffma2(acc, v.y, w.y);
            w = wr[3]; v = hr[3]; ffma2(acc, v.x, w.x); ffma2(acc, v.y, w.y);
            float lo, hi; unpack2(lo, hi, acc);
            og[n * 4 + j] = fmaxf(lo + hi + sagg2g[n * 4 + j] + sW[480 + j], 0.f);
        }
        bar64(1 + wg);           // walks done before list reset
        if (tid64 < NPG) sheadg[tid64] = -1;
        __syncthreads();         // all compute done before next prefetch reuse
        cur ^= 1;
    }
}

// ============================================================================
// Kernel 2: batched out-MLP + global MLP (R7 form — measured best).
// 32 graphs/CTA, 256 threads, 4 CTAs/SM; col pair (p, p+64) x 8 graphs/thread.
// ============================================================================
__global__ void __launch_bounds__(256, 4) mlp_kernel(
    const float* __restrict__ gf,
    const float* __restrict__ Wg1, const float* __restrict__ bg1,
    const float* __restrict__ Wg2, const float* __restrict__ bg2,
    const float* __restrict__ Wg3, const float* __restrict__ bg3,
    const float* __restrict__ bo1,
    const float* __restrict__ Wo2, const float* __restrict__ bo2,
    float* __restrict__ out)
{
    __shared__ __align__(16) float sG[32 * OSTRIDE];   // 29,696 B (reused for reduce)
    __shared__ float sRed[8][32];
    __shared__ float s1[32][8];
    __shared__ float s2[32][8];

    const int tid = threadIdx.x;
    const int p   = tid & 63;           // column pair: p, p+64
    const int q   = tid >> 6;           // graphs q*8 .. q*8+7
    const int b0  = blockIdx.x * 32;

    // ---- issue cp.async stage of 32 scratch rows (embeds) ----
    {
        uint32_t base = smem_u32(sG);
        const float* src = g_scratch + (size_t)b0 * OSTRIDE;
        for (int i = tid; i < 32 * (OSTRIDE / 4); i += 256)
            cpa16(base + i * 16, src + i * 4);
        cpa_commit();
    }

    // ---- global MLP layers 1+2 while staging is in flight ----
    {
        int gg = tid >> 3, jj = tid & 7;               // 32 x 8
        const float* gfr = gf + (size_t)(b0 + gg) * 10;
        float a = bg1[jj];
        #pragma unroll
        for (int k = 0; k < 10; k++) a += gfr[k] * Wg1[k * 8 + jj];
        s1[gg][jj] = fmaxf(a, 0.f);
    }
    __syncthreads();
    {
        int gg = tid >> 3, jj = tid & 7;
        float a = bg2[jj];
        #pragma unroll
        for (int k = 0; k < 8; k++) a += s1[gg][k] * Wg2[k * 8 + jj];
        s2[gg][jj] = fmaxf(a, 0.f);
    }
    cpa_wait0();
    __syncthreads();
    // ---- layer 3 -> sG cols 216..225 ----
    for (int i = tid; i < 320; i += 256) {
        int gg = i / 10, jj = i - gg * 10;
        float a = bg3[jj];
        #pragma unroll
        for (int k = 0; k < 8; k++) a += s2[gg][k] * Wg3[k * 10 + jj];
        sG[gg * OSTRIDE + 216 + jj] = fmaxf(a, 0.f);
    }
    __syncthreads();

    // ---- GEMM: 226 x 128; 2 columns x 8 graphs per thread ----
    unsigned long long accA[8], accB[8];
    #pragma unroll
    for (int g = 0; g < 8; g++) { accA[g] = 0ull; accB[g] = 0ull; }

    const float* wrowA = g_Wo1T + p * 228;          // contiguous column p
    const float* wrowB = g_Wo1T + (p + 64) * 228;   // contiguous column p+64
    const float* gbase = sG + q * 8 * OSTRIDE;

    for (int kc = 0; kc < 224; kc += 8) {
        ulonglong2 wa0 = *reinterpret_cast<const ulonglong2*>(wrowA + kc);
        ulonglong2 wa1 = *reinterpret_cast<const ulonglong2*>(wrowA + kc + 4);
        ulonglong2 wb0 = *reinterpret_cast<const ulonglong2*>(wrowB + kc);
        ulonglong2 wb1 = *reinterpret_cast<const ulonglong2*>(wrowB + kc + 4);
        #pragma unroll
        for (int g = 0; g < 8; g++) {
            const ulonglong2* pp = reinterpret_cast<const ulonglong2*>(gbase + g * OSTRIDE + kc);
            ulonglong2 va = pp[0];
            ulonglong2 vb = pp[1];
            ffma2(accA[g], va.x, wa0.x);
            ffma2(accA[g], va.y, wa0.y);
            ffma2(accA[g], vb.x, wa1.x);
            ffma2(accA[g], vb.y, wa1.y);
            ffma2(accB[g], va.x, wb0.x);
            ffma2(accB[g], va.y, wb0.y);
            ffma2(accB[g], vb.x, wb1.x);
            ffma2(accB[g], vb.y, wb1.y);
        }
    }
    {   // tail: k = 224, 225
        unsigned long long wa = *reinterpret_cast<const unsigned long long*>(wrowA + 224);
        unsigned long long wb = *reinterpret_cast<const unsigned long long*>(wrowB + 224);
        #pragma unroll
        for (int g = 0; g < 8; g++) {
            unsigned long long v = *reinterpret_cast<const unsigned long long*>(gbase + g * OSTRIDE + 224);
            ffma2(accA[g], v, wa);
            ffma2(accB[g], v, wb);
        }
    }

    const float bjA  = bo1[p];
    const float bjB  = bo1[p + 64];
    const float w2A  = Wo2[p];
    const float w2B  = Wo2[p + 64];
    const float bo2v = bo2[0];

    __syncthreads();   // done reading sG; reuse for partial products
    #pragma unroll
    for (int g = 0; g < 8; g++) {
        float lo, hi; unpack2(lo, hi, accA[g]);
        sG[p * 33 + q * 8 + g] = fmaxf(lo + hi + bjA, 0.f) * w2A;
        unpack2(lo, hi, accB[g]);
        sG[(p + 64) * 33 + q * 8 + g] = fmaxf(lo + hi + bjB, 0.f) * w2B;
    }
    __syncthreads();

    {   // reduce over columns: 8 chunks of 16 columns each
        int g = tid & 31, qq = tid >> 5;
        float s = 0.f;
        #pragma unroll
        for (int jj = 0; jj < 16; jj++) s += sG[(qq * 16 + jj) * 33 + g];
        sRed[qq][g] = s;
    }
    __syncthreads();
    if (tid < 32) {
        float z = sRed[0][tid] + sRed[1][tid] + sRed[2][tid] + sRed[3][tid]
                + sRed[4][tid] + sRed[5][tid] + sRed[6][tid] + sRed[7][tid] + bo2v;
        out[b0 + tid] = 1.f / (1.f + expf(-z));
    }
}

// ============================================================================
extern "C" void kernel_launch(void* const* d_in, const int* in_sizes, int n_in,
                              void* d_out, int out_size) {
    (void)in_sizes; (void)n_in; (void)out_size;
    const float* x      = (const float*)d_in[0];
    const int*   ei     = (const int*)  d_in[1];
    const float* ea     = (const float*)d_in[2];
    const float* gfeats = (const float*)d_in[3];
    const float* Wrel1  = (const float*)d_in[4];
    const float* b1     = (const float*)d_in[5];
    const float* Wroot1 = (const float*)d_in[6];
    const float* Wrel2  = (const float*)d_in[7];
    const float* b2     = (const float*)d_in[8];
    const float* Wroot2 = (const float*)d_in[9];
    const float* Wg1    = (const float*)d_in[10];
    const float* bg1    = (const float*)d_in[11];
    const float* Wg2    = (const float*)d_in[12];
    const float* bg2    = (const float*)d_in[13];
    const float* Wg3    = (const float*)d_in[14];
    const float* bg3    = (const float*)d_in[15];
    const float* Wo1    = (const float*)d_in[16];
    const float* bo1    = (const float*)d_in[17];
    const float* Wo2    = (const float*)d_in[18];
    const float* bo2    = (const float*)d_in[19];
    float* out = (float*)d_out;

    gnn_kernel<<<GNN_GRID, 128>>>(x, ei, ea,
                                  Wrel1, b1, Wroot1, Wrel2, b2, Wroot2, Wo1);
    mlp_kernel<<<BGRAPH / 32, 256>>>(gfeats, Wg1, bg1, Wg2, bg2, Wg3, bg3,
                                     bo1, Wo2, bo2, out);
}

// round 12
// speedup vs baseline: 1.0479x; 1.0479x over previous
#include <cuda_runtime.h>
#include <math.h>
#include <stdint.h>

#define BGRAPH  32768
#define NPG     54
#define EPG     144
#define NTOT    (BGRAPH*NPG)
#define ETOT    (BGRAPH*EPG)
#define OSTRIDE 232            // 226 used, padded
#define GNN_GRID 1184          // 8 * 148: one wave

// Scratch: embeds(216) per graph (mlp fills cols 216..225 itself).
__device__ __align__(16) float g_scratch[(size_t)BGRAPH * OSTRIDE];
// Column-major padded Wo1^T: [128 cols][228], built by gnn CTAs.
__device__ __align__(16) float g_Wo1T[128 * 228 + 16];

// ---------- packed fp32x2 helpers ----------
__device__ __forceinline__ void ffma2(unsigned long long& d,
                                      unsigned long long a,
                                      unsigned long long b) {
    asm("fma.rn.f32x2 %0, %1, %2, %0;" : "+l"(d) : "l"(a), "l"(b));
}
__device__ __forceinline__ unsigned long long pack2(float lo, float hi) {
    unsigned long long r;
    asm("mov.b64 %0, {%1, %2};" : "=l"(r) : "f"(lo), "f"(hi));
    return r;
}
__device__ __forceinline__ void unpack2(float& lo, float& hi, unsigned long long v) {
    asm("mov.b64 {%0, %1}, %2;" : "=f"(lo), "=f"(hi) : "l"(v));
}

// ---------- cp.async helpers ----------
__device__ __forceinline__ uint32_t smem_u32(const void* p) {
    return (uint32_t)__cvta_generic_to_shared(p);
}
__device__ __forceinline__ void cpa16(uint32_t s, const void* g) {
    asm volatile("cp.async.cg.shared.global [%0], [%1], 16;" :: "r"(s), "l"(g));
}
__device__ __forceinline__ void cpa_commit() {
    asm volatile("cp.async.commit_group;");
}
__device__ __forceinline__ void cpa_wait0() {
    asm volatile("cp.async.wait_group 0;");
}
__device__ __forceinline__ void cpa_wait1() {
    asm volatile("cp.async.wait_group 1;");
}

// ============================================================================
// Kernel 1 (R8 structure — measured best gnn): persistent CTAs, cp.async
// double buffer, warp-fused conv+lin, conv2 pre-transformed to 4-wide.
// ============================================================================
#define BUF_F   864
#define BUF_X   0
#define BUF_SRC 432
#define BUF_DST 576
#define BUF_EA  720

__global__ void __launch_bounds__(128, 8) gnn_kernel(
    const float* __restrict__ x,  const int* __restrict__ ei,
    const float* __restrict__ ea,
    const float* __restrict__ Wrel1, const float* __restrict__ b1,
    const float* __restrict__ Wroot1,
    const float* __restrict__ Wrel2, const float* __restrict__ b2,
    const float* __restrict__ Wroot2,
    const float* __restrict__ Wo1)
{
    __shared__ __align__(16) float sW[484];
    __shared__ __align__(16) float sh1[NPG * 16];
    __shared__ __align__(16) float sagg1[NPG * 8];   // conv1 agg; reused as h2pre [54x4]
    __shared__ __align__(16) float sagg2[NPG * 4];   // conv2 agg (4-wide)
    __shared__ int   shead[NPG];
    __shared__ int   snext[EPG];
    __shared__ int   ssrc[EPG];
    __shared__ __align__(16) float buf[2][BUF_F];

    const int tid  = threadIdx.x;
    const int wid  = tid >> 5;
    const int lane = tid & 31;
    const int nstart = (wid < 2) ? wid * 14 : 28 + (wid - 2) * 13;
    const int ncnt   = (wid < 2) ? 14 : 13;

    // ---- build Wo1T cooperatively (write-once, consumed by mlp_kernel) ----
    {
        int gt = blockIdx.x * 128 + tid;
        if (gt < 226 * 128) {
            int j = gt / 226, k = gt - j * 226;
            g_Wo1T[j * 228 + k] = Wo1[k * 128 + j];
        }
    }

    // ---- build local transposed weights ----
    #pragma unroll
    for (int i = tid; i < 256; i += 128) {          // WT1
        int j = i >> 4, k = i & 15;
        sW[j * 20 + k] = (k < 8) ? Wrel1[k * 16 + j] : Wroot1[(k - 8) * 16 + j];
    }
    if (tid < 16) sW[320 + tid] = b1[tid];
    {                                               // WT2
        int j = tid >> 5, k = tid & 31;
        sW[336 + j * 36 + k] = (k < 16) ? Wrel2[k * 4 + j] : Wroot2[(k - 16) * 4 + j];
    }
    if (tid < 4)  sW[480 + tid] = b2[tid];
    if (tid < NPG) shead[tid] = -1;

    // ---- prefetch first graph ----
    int g0 = blockIdx.x;
    {
        uint32_t base = smem_u32(&buf[0][0]);
        const float* xg = x + (size_t)g0 * (NPG * 8);
        const int*   sg = ei + (size_t)g0 * EPG;
        const int*   dg = ei + (size_t)ETOT + (size_t)g0 * EPG;
        const float* eg = ea + (size_t)g0 * EPG;
        for (int i = tid; i < 216; i += 128) {
            if (i < 108)      cpa16(base + (BUF_X * 4)   + i * 16,        xg + i * 4);
            else if (i < 144) cpa16(base + (BUF_SRC * 4) + (i - 108) * 16, sg + (i - 108) * 4);
            else if (i < 180) cpa16(base + (BUF_DST * 4) + (i - 144) * 16, dg + (i - 144) * 4);
            else              cpa16(base + (BUF_EA * 4)  + (i - 180) * 16, eg + (i - 180) * 4);
        }
    }
    cpa_commit();

    int cur = 0;
    for (int g = g0; g < BGRAPH; g += GNN_GRID) {
        int gn = g + GNN_GRID;
        if (gn < BGRAPH) {       // prefetch next into other buffer
            uint32_t base = smem_u32(&buf[cur ^ 1][0]);
            const float* xg = x + (size_t)gn * (NPG * 8);
            const int*   sg = ei + (size_t)gn * EPG;
            const int*   dg = ei + (size_t)ETOT + (size_t)gn * EPG;
            const float* eg = ea + (size_t)gn * EPG;
            for (int i = tid; i < 216; i += 128) {
                if (i < 108)      cpa16(base + (BUF_X * 4)   + i * 16,        xg + i * 4);
                else if (i < 144) cpa16(base + (BUF_SRC * 4) + (i - 108) * 16, sg + (i - 108) * 4);
                else if (i < 180) cpa16(base + (BUF_DST * 4) + (i - 144) * 16, dg + (i - 144) * 4);
                else              cpa16(base + (BUF_EA * 4)  + (i - 180) * 16, eg + (i - 180) * 4);
            }
            cpa_commit();
            cpa_wait1();
        } else {
            cpa_wait0();
        }
        __syncthreads();         // buffer + shead reset visible

        const float* bx  = &buf[cur][BUF_X];
        const int*   bs  = (const int*)&buf[cur][BUF_SRC];
        const int*   bd  = (const int*)&buf[cur][BUF_DST];
        const float* bea = &buf[cur][BUF_EA];
        const int nbase = g * NPG;

        // ---- build per-destination edge linked lists ----
        for (int e = tid; e < EPG; e += 128) {
            int d = bd[e] - nbase;
            ssrc[e]  = bs[e] - nbase;
            snext[e] = atomicExch(&shead[d], e);
        }
        __syncthreads();

        // ---- warp-fused conv1 + lin1 over this warp's nodes ----
        for (int i = lane; i < ncnt * 2; i += 32) {
            int d = nstart + (i >> 1), c = i & 1;
            unsigned long long a0 = 0ull, a1 = 0ull;
            for (int e = shead[d]; e >= 0; e = snext[e]) {
                unsigned long long ap = pack2(bea[e], bea[e]);
                ulonglong2 v = *reinterpret_cast<const ulonglong2*>(bx + ssrc[e] * 8 + c * 4);
                ffma2(a0, v.x, ap); ffma2(a1, v.y, ap);
            }
            ulonglong2 r; r.x = a0; r.y = a1;
            *reinterpret_cast<ulonglong2*>(sagg1 + d * 8 + c * 4) = r;
        }
        __syncwarp();
        for (int i = lane; i < ncnt * 16; i += 32) {
            int n = nstart + (i >> 4), j = i & 15;
            const ulonglong2* ar = reinterpret_cast<const ulonglong2*>(sagg1 + n * 8);
            const ulonglong2* xr = reinterpret_cast<const ulonglong2*>(bx + n * 8);
            const ulonglong2* wr = reinterpret_cast<const ulonglong2*>(sW + j * 20);
            unsigned long long acc = 0ull;
            ulonglong2 w0 = wr[0], w1 = wr[1], w2 = wr[2], w3 = wr[3];
            ulonglong2 aa0 = ar[0], aa1 = ar[1], xx0 = xr[0], xx1 = xr[1];
            ffma2(acc, aa0.x, w0.x); ffma2(acc, aa0.y, w0.y);
            ffma2(acc, aa1.x, w1.x); ffma2(acc, aa1.y, w1.y);
            ffma2(acc, xx0.x, w2.x); ffma2(acc, xx0.y, w2.y);
            ffma2(acc, xx1.x, w3.x); ffma2(acc, xx1.y, w3.y);
            float lo, hi; unpack2(lo, hi, acc);
            sh1[n * 16 + j] = fmaxf(lo + hi + sW[320 + j], 0.f);
        }
        __syncthreads();         // all sh1 complete; all lin1 reads of sagg1 done

        // ---- h2pre = h1 @ Wrel2 for this warp's nodes (into sagg1 [54x4]) ----
        for (int i = lane; i < ncnt * 4; i += 32) {
            int n = nstart + (i >> 2), j = i & 3;
            const ulonglong2* hr = reinterpret_cast<const ulonglong2*>(sh1 + n * 16);
            const ulonglong2* wr = reinterpret_cast<const ulonglong2*>(sW + 336 + j * 36);
            unsigned long long acc = 0ull;
            ulonglong2 w, v;
            w = wr[0]; v = hr[0]; ffma2(acc, v.x, w.x); ffma2(acc, v.y, w.y);
            w = wr[1]; v = hr[1]; ffma2(acc, v.x, w.x); ffma2(acc, v.y, w.y);
            w = wr[2]; v = hr[2]; ffma2(acc, v.x, w.x); ffma2(acc, v.y, w.y);
            w = wr[3]; v = hr[3]; ffma2(acc, v.x, w.x); ffma2(acc, v.y, w.y);
            float lo, hi; unpack2(lo, hi, acc);
            sagg1[n * 4 + j] = lo + hi;
        }
        __syncthreads();         // h2pre complete (walk reads cross-warp nodes)

        // ---- conv2 aggregation, 4-wide: acc pair (2j,2j+1) per thread ----
        for (int i = lane; i < ncnt * 2; i += 32) {
            int d = nstart + (i >> 1), jp = i & 1;
            unsigned long long acc = 0ull;
            for (int e = shead[d]; e >= 0; e = snext[e]) {
                unsigned long long ap = pack2(bea[e], bea[e]);
                unsigned long long v = *reinterpret_cast<const unsigned long long*>(
                    sagg1 + ssrc[e] * 4 + jp * 2);
                ffma2(acc, v, ap);
            }
            *reinterpret_cast<unsigned long long*>(sagg2 + d * 4 + jp * 2) = acc;
        }
        __syncwarp();

        // ---- lin2 (root half): og = relu(agg + h1 @ Wroot2 + b2) ----
        float* og = g_scratch + (size_t)g * OSTRIDE;
        for (int i = lane; i < ncnt * 4; i += 32) {
            int n = nstart + (i >> 2), j = i & 3;
            const ulonglong2* hr = reinterpret_cast<const ulonglong2*>(sh1 + n * 16);
            const ulonglong2* wr = reinterpret_cast<const ulonglong2*>(sW + 336 + j * 36 + 16);
            unsigned long long acc = 0ull;
            ulonglong2 w, v;
            w = wr[0]; v = hr[0]; ffma2(acc, v.x, w.x); ffma2(acc, v.y, w.y);
            w = wr[1]; v = hr[1]; ffma2(acc, v.x, w.x); ffma2(acc, v.y, w.y);
            w = wr[2]; v = hr[2]; ffma2(acc, v.x, w.x); ffma2(acc, v.y, w.y);
            w = wr[3]; v = hr[3]; ffma2(acc, v.x, w.x); ffma2(acc, v.y, w.y);
            float lo, hi; unpack2(lo, hi, acc);
            og[n * 4 + j] = fmaxf(lo + hi + sagg2[n * 4 + j] + sW[480 + j], 0.f);
        }
        __syncthreads();   // all walks + compute done before buffer/list reuse
        if (tid < NPG) shead[tid] = -1;   // reset for next graph
        cur ^= 1;
    }
}

// ============================================================================
// Kernel 2 (R7/R10 form — measured best mlp): batched out-MLP + global MLP.
// 32 graphs/CTA, 256 threads, 4 CTAs/SM; col pair (p, p+64) x 8 graphs/thread.
// ============================================================================
__global__ void __launch_bounds__(256, 4) mlp_kernel(
    const float* __restrict__ gf,
    const float* __restrict__ Wg1, const float* __restrict__ bg1,
    const float* __restrict__ Wg2, const float* __restrict__ bg2,
    const float* __restrict__ Wg3, const float* __restrict__ bg3,
    const float* __restrict__ bo1,
    const float* __restrict__ Wo2, const float* __restrict__ bo2,
    float* __restrict__ out)
{
    __shared__ __align__(16) float sG[32 * OSTRIDE];   // 29,696 B (reused for reduce)
    __shared__ float sRed[8][32];
    __shared__ float s1[32][8];
    __shared__ float s2[32][8];

    const int tid = threadIdx.x;
    const int p   = tid & 63;           // column pair: p, p+64
    const int q   = tid >> 6;           // graphs q*8 .. q*8+7
    const int b0  = blockIdx.x * 32;

    // ---- issue cp.async stage of 32 scratch rows (embeds) ----
    {
        uint32_t base = smem_u32(sG);
        const float* src = g_scratch + (size_t)b0 * OSTRIDE;
        for (int i = tid; i < 32 * (OSTRIDE / 4); i += 256)
            cpa16(base + i * 16, src + i * 4);
        cpa_commit();
    }

    // ---- global MLP layers 1+2 while staging is in flight ----
    {
        int gg = tid >> 3, jj = tid & 7;               // 32 x 8
        const float* gfr = gf + (size_t)(b0 + gg) * 10;
        float a = bg1[jj];
        #pragma unroll
        for (int k = 0; k < 10; k++) a += gfr[k] * Wg1[k * 8 + jj];
        s1[gg][jj] = fmaxf(a, 0.f);
    }
    __syncthreads();
    {
        int gg = tid >> 3, jj = tid & 7;
        float a = bg2[jj];
        #pragma unroll
        for (int k = 0; k < 8; k++) a += s1[gg][k] * Wg2[k * 8 + jj];
        s2[gg][jj] = fmaxf(a, 0.f);
    }
    cpa_wait0();
    __syncthreads();
    // ---- layer 3 -> sG cols 216..225 ----
    for (int i = tid; i < 320; i += 256) {
        int gg = i / 10, jj = i - gg * 10;
        float a = bg3[jj];
        #pragma unroll
        for (int k = 0; k < 8; k++) a += s2[gg][k] * Wg3[k * 10 + jj];
        sG[gg * OSTRIDE + 216 + jj] = fmaxf(a, 0.f);
    }
    __syncthreads();

    // ---- GEMM: 226 x 128; 2 columns x 8 graphs per thread ----
    unsigned long long accA[8], accB[8];
    #pragma unroll
    for (int g = 0; g < 8; g++) { accA[g] = 0ull; accB[g] = 0ull; }

    const float* wrowA = g_Wo1T + p * 228;          // contiguous column p
    const float* wrowB = g_Wo1T + (p + 64) * 228;   // contiguous column p+64
    const float* gbase = sG + q * 8 * OSTRIDE;

    for (int kc = 0; kc < 224; kc += 8) {
        ulonglong2 wa0 = *reinterpret_cast<const ulonglong2*>(wrowA + kc);
        ulonglong2 wa1 = *reinterpret_cast<const ulonglong2*>(wrowA + kc + 4);
        ulonglong2 wb0 = *reinterpret_cast<const ulonglong2*>(wrowB + kc);
        ulonglong2 wb1 = *reinterpret_cast<const ulonglong2*>(wrowB + kc + 4);
        #pragma unroll
        for (int g = 0; g < 8; g++) {
            const ulonglong2* pp = reinterpret_cast<const ulonglong2*>(gbase + g * OSTRIDE + kc);
            ulonglong2 va = pp[0];
            ulonglong2 vb = pp[1];
            ffma2(accA[g], va.x, wa0.x);
            ffma2(accA[g], va.y, wa0.y);
            ffma2(accA[g], vb.x, wa1.x);
            ffma2(accA[g], vb.y, wa1.y);
            ffma2(accB[g], va.x, wb0.x);
            ffma2(accB[g], va.y, wb0.y);
            ffma2(accB[g], vb.x, wb1.x);
            ffma2(accB[g], vb.y, wb1.y);
        }
    }
    {   // tail: k = 224, 225
        unsigned long long wa = *reinterpret_cast<const unsigned long long*>(wrowA + 224);
        unsigned long long wb = *reinterpret_cast<const unsigned long long*>(wrowB + 224);
        #pragma unroll
        for (int g = 0; g < 8; g++) {
            unsigned long long v = *reinterpret_cast<const unsigned long long*>(gbase + g * OSTRIDE + 224);
            ffma2(accA[g], v, wa);
            ffma2(accB[g], v, wb);
        }
    }

    const float bjA  = bo1[p];
    const float bjB  = bo1[p + 64];
    const float w2A  = Wo2[p];
    const float w2B  = Wo2[p + 64];
    const float bo2v = bo2[0];

    __syncthreads();   // done reading sG; reuse for partial products
    #pragma unroll
    for (int g = 0; g < 8; g++) {
        float lo, hi; unpack2(lo, hi, accA[g]);
        sG[p * 33 + q * 8 + g] = fmaxf(lo + hi + bjA, 0.f) * w2A;
        unpack2(lo, hi, accB[g]);
        sG[(p + 64) * 33 + q * 8 + g] = fmaxf(lo + hi + bjB, 0.f) * w2B;
    }
    __syncthreads();

    {   // reduce over columns: 8 chunks of 16 columns each
        int g = tid & 31, qq = tid >> 5;
        float s = 0.f;
        #pragma unroll
        for (int jj = 0; jj < 16; jj++) s += sG[(qq * 16 + jj) * 33 + g];
        sRed[qq][g] = s;
    }
    __syncthreads();
    if (tid < 32) {
        float z = sRed[0][tid] + sRed[1][tid] + sRed[2][tid] + sRed[3][tid]
                + sRed[4][tid] + sRed[5][tid] + sRed[6][tid] + sRed[7][tid] + bo2v;
        out[b0 + tid] = 1.f / (1.f + expf(-z));
    }
}

// ============================================================================
extern "C" void kernel_launch(void* const* d_in, const int* in_sizes, int n_in,
                              void* d_out, int out_size) {
    (void)in_sizes; (void)n_in; (void)out_size;
    const float* x      = (const float*)d_in[0];
    const int*   ei     = (const int*)  d_in[1];
    const float* ea     = (const float*)d_in[2];
    const float* gfeats = (const float*)d_in[3];
    const float* Wrel1  = (const float*)d_in[4];
    const float* b1     = (const float*)d_in[5];
    const float* Wroot1 = (const float*)d_in[6];
    const float* Wrel2  = (const float*)d_in[7];
    const float* b2     = (const float*)d_in[8];
    const float* Wroot2 = (const float*)d_in[9];
    const float* Wg1    = (const float*)d_in[10];
    const float* bg1    = (const float*)d_in[11];
    const float* Wg2    = (const float*)d_in[12];
    const float* bg2    = (const float*)d_in[13];
    const float* Wg3    = (const float*)d_in[14];
    const float* bg3    = (const float*)d_in[15];
    const float* Wo1    = (const float*)d_in[16];
    const float* bo1    = (const float*)d_in[17];
    const float* Wo2    = (const float*)d_in[18];
    const float* bo2    = (const float*)d_in[19];
    float* out = (float*)d_out;

    gnn_kernel<<<GNN_GRID, 128>>>(x, ei, ea,
                                  Wrel1, b1, Wroot1, Wrel2, b2, Wroot2, Wo1);
    mlp_kernel<<<BGRAPH / 32, 256>>>(gfeats, Wg1, bg1, Wg2, bg2, Wg3, bg3,
                                     bo1, Wo2, bo2, out);
}